// round 2
// baseline (speedup 1.0000x reference)
#include <cuda_runtime.h>
#include <math.h>

// Problem constants: x, ref are [16, 3, 512, 512] fp32.
#define NIMG   48          // B*C
#define HH     512
#define WW     512
#define IMG    (HH * WW)   // 262144 floats per image
#define CHUNK  32          // rows per CTA in kernel 1
#define NCHUNK (HH / CHUNK)        // 16
#define NCTA1  (NIMG * NCHUNK)     // 768
#define ROWS_PER_WARP (CHUNK / 8)  // 4 (8 warps / CTA)
#define EPSN   1e-12f

// Scratch: written fully every launch, never needs zero-init.
__device__ float  g_colPart[NIMG][NCHUNK][3][WW];  // per-chunk column partials: dot, sum x^2, sum r^2
__device__ float  g_rowPart[NCTA1];                // per-CTA sum of row cosines
__device__ double g_imgColSum[NIMG];               // per-image sum of column cosines

// ---------------------------------------------------------------------------
// Kernel 1: single pass over the data. Each CTA = (image, 32-row chunk).
//   - row cosines finished in-CTA (warp owns 4 rows, full-width shuffle reduce)
//   - column partials (dot, sx, sr) accumulated in registers (16 fixed columns
//     per thread), merged across warps via shared atomics, stored to scratch.
// ---------------------------------------------------------------------------
__global__ __launch_bounds__(256) void spl_pass1(const float* __restrict__ x,
                                                 const float* __restrict__ ref)
{
    const int bid   = blockIdx.x;
    const int img   = bid / NCHUNK;
    const int chunk = bid % NCHUNK;
    const int tid   = threadIdx.x;
    const int lane  = tid & 31;
    const int warp  = tid >> 5;

    __shared__ float sCol[3][WW];
    __shared__ float sRow[8];

    // zero shared column accumulators (visible to atomics after the syncthreads below)
    for (int i = tid; i < 3 * WW; i += 256)
        (&sCol[0][0])[i] = 0.0f;

    const float4* __restrict__ xb = (const float4*)(x   + (size_t)img * IMG);
    const float4* __restrict__ rb = (const float4*)(ref + (size_t)img * IMG);

    // per-thread column accumulators: columns (k*32+lane)*4 + j, k=0..3, j=0..3
    float cd[16], cx[16], cr[16];
#pragma unroll
    for (int i = 0; i < 16; i++) { cd[i] = 0.f; cx[i] = 0.f; cr[i] = 0.f; }

    float rowAcc = 0.0f;
    const int r0 = chunk * CHUNK + warp * ROWS_PER_WARP;

#pragma unroll
    for (int i = 0; i < ROWS_PER_WARP; i++) {
        const int r = r0 + i;
        const float4* __restrict__ xr = xb + r * (WW / 4);
        const float4* __restrict__ rr = rb + r * (WW / 4);

        float4 xv[4], rv[4];
#pragma unroll
        for (int k = 0; k < 4; k++) {
            xv[k] = xr[k * 32 + lane];
            rv[k] = rr[k * 32 + lane];
        }

        float rd = 0.f, rx = 0.f, rs = 0.f;
#pragma unroll
        for (int k = 0; k < 4; k++) {
            float a, b;
            a = xv[k].x; b = rv[k].x;
            rd += a * b; rx += a * a; rs += b * b;
            cd[k*4+0] += a * b; cx[k*4+0] += a * a; cr[k*4+0] += b * b;
            a = xv[k].y; b = rv[k].y;
            rd += a * b; rx += a * a; rs += b * b;
            cd[k*4+1] += a * b; cx[k*4+1] += a * a; cr[k*4+1] += b * b;
            a = xv[k].z; b = rv[k].z;
            rd += a * b; rx += a * a; rs += b * b;
            cd[k*4+2] += a * b; cx[k*4+2] += a * a; cr[k*4+2] += b * b;
            a = xv[k].w; b = rv[k].w;
            rd += a * b; rx += a * a; rs += b * b;
            cd[k*4+3] += a * b; cx[k*4+3] += a * a; cr[k*4+3] += b * b;
        }

        // full-warp reduce (all lanes end with the same value)
#pragma unroll
        for (int o = 16; o > 0; o >>= 1) {
            rd += __shfl_xor_sync(0xFFFFFFFFu, rd, o);
            rx += __shfl_xor_sync(0xFFFFFFFFu, rx, o);
            rs += __shfl_xor_sync(0xFFFFFFFFu, rs, o);
        }
        const float denom = fmaxf(sqrtf(rx), EPSN) * fmaxf(sqrtf(rs), EPSN);
        rowAcc += rd / denom;
    }

    if (lane == 0) sRow[warp] = rowAcc;
    __syncthreads();  // orders: sCol zeroing + sRow writes  before  atomics/reads

    // merge per-thread column partials across the 8 warps
#pragma unroll
    for (int k = 0; k < 4; k++) {
#pragma unroll
        for (int j = 0; j < 4; j++) {
            const int col = (k * 32 + lane) * 4 + j;
            atomicAdd(&sCol[0][col], cd[k * 4 + j]);
            atomicAdd(&sCol[1][col], cx[k * 4 + j]);
            atomicAdd(&sCol[2][col], cr[k * 4 + j]);
        }
    }
    __syncthreads();

    // coalesced store of the 3x512 partials for this (image, chunk)
    for (int i = tid; i < 3 * WW; i += 256) {
        const int c = i >> 9;       // /512
        const int w = i & (WW - 1); // %512
        g_colPart[img][chunk][c][w] = sCol[c][w];
    }
    if (tid == 0) {
        float s = 0.f;
#pragma unroll
        for (int wv = 0; wv < 8; wv++) s += sRow[wv];
        g_rowPart[bid] = s;
    }
}

// ---------------------------------------------------------------------------
// Kernel 2: finish columns. One CTA per image, one thread per column.
// ---------------------------------------------------------------------------
__global__ __launch_bounds__(512) void spl_pass2()
{
    const int img = blockIdx.x;
    const int w   = threadIdx.x;

    float d = 0.f, sx = 0.f, sr = 0.f;
#pragma unroll
    for (int ch = 0; ch < NCHUNK; ch++) {
        d  += g_colPart[img][ch][0][w];
        sx += g_colPart[img][ch][1][w];
        sr += g_colPart[img][ch][2][w];
    }
    const float denom = fmaxf(sqrtf(sx), EPSN) * fmaxf(sqrtf(sr), EPSN);
    double c = (double)(d / denom);

    // block reduce in double
    __shared__ double sred[16];
    const int lane = w & 31, wp = w >> 5;
#pragma unroll
    for (int o = 16; o > 0; o >>= 1)
        c += __shfl_xor_sync(0xFFFFFFFFu, c, o);
    if (lane == 0) sred[wp] = c;
    __syncthreads();
    if (wp == 0) {
        double v = (lane < 16) ? sred[lane] : 0.0;
#pragma unroll
        for (int o = 8; o > 0; o >>= 1)
            v += __shfl_xor_sync(0xFFFFFFFFu, v, o);
        if (lane == 0) g_imgColSum[img] = v;
    }
}

// ---------------------------------------------------------------------------
// Kernel 3: final scalar.  out = -(rowSum + colSum) / (B*H)   (B=16, H=W=512)
// ---------------------------------------------------------------------------
__global__ __launch_bounds__(256) void spl_pass3(float* __restrict__ out)
{
    const int t = threadIdx.x;
    double s = 0.0;
    for (int i = t; i < NCTA1; i += 256) s += (double)g_rowPart[i];
    if (t < NIMG) s += g_imgColSum[t];

    __shared__ double sred[8];
    const int lane = t & 31, wp = t >> 5;
#pragma unroll
    for (int o = 16; o > 0; o >>= 1)
        s += __shfl_xor_sync(0xFFFFFFFFu, s, o);
    if (lane == 0) sred[wp] = s;
    __syncthreads();
    if (wp == 0) {
        double v = (lane < 8) ? sred[lane] : 0.0;
#pragma unroll
        for (int o = 4; o > 0; o >>= 1)
            v += __shfl_xor_sync(0xFFFFFFFFu, v, o);
        if (lane == 0) out[0] = (float)(-v / 8192.0);
    }
}

extern "C" void kernel_launch(void* const* d_in, const int* in_sizes, int n_in,
                              void* d_out, int out_size)
{
    const float* x   = (const float*)d_in[0];
    const float* ref = (const float*)d_in[1];
    float* out = (float*)d_out;

    spl_pass1<<<NCTA1, 256>>>(x, ref);
    spl_pass2<<<NIMG, 512>>>();
    spl_pass3<<<1, 256>>>(out);
}

// round 4
// speedup vs baseline: 1.6835x; 1.6835x over previous
#include <cuda_runtime.h>
#include <math.h>

// Problem constants: x, ref are [16, 3, 512, 512] fp32.
#define NIMG   48          // B*C
#define HH     512
#define WW     512
#define IMG    (HH * WW)   // 262144 floats per image
#define WF4    (WW / 4)    // 128 float4 per row
#define CHUNK  32          // rows per CTA in kernel 1
#define NCHUNK (HH / CHUNK)        // 16
#define NCTA1  (NIMG * NCHUNK)     // 768
#define EPSN   1e-12f

// Scratch: written fully every launch, never needs zero-init.
__device__ float        g_colPart[NIMG][NCHUNK][3][WW]; // per-chunk column partials
__device__ float        g_rowPart[NCTA1];               // per-CTA sum of row cosines
__device__ double       g_imgColSum[NIMG];              // per-image sum of column cosines
__device__ unsigned int g_cnt;                          // last-block counter (reset in pass1)

__device__ __forceinline__ float warp_sum(float v)
{
#pragma unroll
    for (int o = 16; o > 0; o >>= 1)
        v += __shfl_xor_sync(0xFFFFFFFFu, v, o);
    return v;
}

// ---------------------------------------------------------------------------
// Kernel 1: single pass. CTA = (image, 32-row chunk), 8 warps.
//   warp w: column half cw = w&1 (64 float4), row group rg = w>>1 (8 rows).
//   Each thread owns 2 FIXED float4 positions (8 columns) -> 24 col-acc regs.
//   Row partials: 2-level shfl butterfly -> lanes 0..7 store to padded shared;
//   full reduction deferred to a one-warp epilogue (no f32 redux on sm_103!).
// ---------------------------------------------------------------------------
__global__ __launch_bounds__(256, 3) void spl_pass1(const float* __restrict__ x,
                                                    const float* __restrict__ ref)
{
    const int bid   = blockIdx.x;
    const int img   = bid / NCHUNK;
    const int chunk = bid % NCHUNK;
    const int tid   = threadIdx.x;
    const int lane  = tid & 31;
    const int w     = tid >> 5;
    const int cw    = w & 1;    // column half (0: cols 0..255, 1: cols 256..511)
    const int rg    = w >> 1;   // row group (8 rows each)

    __shared__ float sColP[8][3][64][4];   // per-warp column partials (24 KB)
    __shared__ float sRL[8][3][8][9];      // per-warp row partials, pad=9 (6.75 KB)

    if (bid == 0 && tid == 0) g_cnt = 0;   // reset last-block counter for pass2

    const int f0 = cw * 64 + lane;         // float4 index of first owned position
    const int rowBase = chunk * CHUNK + rg * 8;

    const float4* __restrict__ xb = (const float4*)(x   + (size_t)img * IMG) + (size_t)rowBase * WF4 + f0;
    const float4* __restrict__ rb = (const float4*)(ref + (size_t)img * IMG) + (size_t)rowBase * WF4 + f0;

    float cda[4], cxa[4], cra[4];   // stats for columns f0*4+j
    float cdb[4], cxb[4], crb[4];   // stats for columns (f0+32)*4+j
#pragma unroll
    for (int j = 0; j < 4; j++) {
        cda[j] = cxa[j] = cra[j] = 0.f;
        cdb[j] = cxb[j] = crb[j] = 0.f;
    }

#pragma unroll 1
    for (int i = 0; i < 8; i++) {
        const float4 xa = xb[i * WF4];
        const float4 xc = xb[i * WF4 + 32];
        const float4 ra = rb[i * WF4];
        const float4 rc = rb[i * WF4 + 32];

        float rd = 0.f, rx = 0.f, rs = 0.f;
        {
            float a, b;
            a = xa.x; b = ra.x; rd += a*b; rx += a*a; rs += b*b; cda[0] += a*b; cxa[0] += a*a; cra[0] += b*b;
            a = xa.y; b = ra.y; rd += a*b; rx += a*a; rs += b*b; cda[1] += a*b; cxa[1] += a*a; cra[1] += b*b;
            a = xa.z; b = ra.z; rd += a*b; rx += a*a; rs += b*b; cda[2] += a*b; cxa[2] += a*a; cra[2] += b*b;
            a = xa.w; b = ra.w; rd += a*b; rx += a*a; rs += b*b; cda[3] += a*b; cxa[3] += a*a; cra[3] += b*b;
            a = xc.x; b = rc.x; rd += a*b; rx += a*a; rs += b*b; cdb[0] += a*b; cxb[0] += a*a; crb[0] += b*b;
            a = xc.y; b = rc.y; rd += a*b; rx += a*a; rs += b*b; cdb[1] += a*b; cxb[1] += a*a; crb[1] += b*b;
            a = xc.z; b = rc.z; rd += a*b; rx += a*a; rs += b*b; cdb[2] += a*b; cxb[2] += a*a; crb[2] += b*b;
            a = xc.w; b = rc.w; rd += a*b; rx += a*a; rs += b*b; cdb[3] += a*b; cxb[3] += a*a; crb[3] += b*b;
        }

        // 2-level butterfly: lanes 0..7 hold disjoint 4-lane group sums
        rd += __shfl_xor_sync(0xFFFFFFFFu, rd, 16);
        rx += __shfl_xor_sync(0xFFFFFFFFu, rx, 16);
        rs += __shfl_xor_sync(0xFFFFFFFFu, rs, 16);
        rd += __shfl_xor_sync(0xFFFFFFFFu, rd, 8);
        rx += __shfl_xor_sync(0xFFFFFFFFu, rx, 8);
        rs += __shfl_xor_sync(0xFFFFFFFFu, rs, 8);
        if (lane < 8) {
            sRL[w][0][i][lane] = rd;
            sRL[w][1][i][lane] = rx;
            sRL[w][2][i][lane] = rs;
        }
    }

    // stage per-warp column partials (conflict-free STS.128)
    *(float4*)&sColP[w][0][lane][0]      = make_float4(cda[0], cda[1], cda[2], cda[3]);
    *(float4*)&sColP[w][1][lane][0]      = make_float4(cxa[0], cxa[1], cxa[2], cxa[3]);
    *(float4*)&sColP[w][2][lane][0]      = make_float4(cra[0], cra[1], cra[2], cra[3]);
    *(float4*)&sColP[w][0][lane + 32][0] = make_float4(cdb[0], cdb[1], cdb[2], cdb[3]);
    *(float4*)&sColP[w][1][lane + 32][0] = make_float4(cxb[0], cxb[1], cxb[2], cxb[3]);
    *(float4*)&sColP[w][2][lane + 32][0] = make_float4(crb[0], crb[1], crb[2], crb[3]);

    __syncthreads();

    // finish rows: one lane per row (row = tid), sum 2 halves x 8 sublanes
    if (tid < 32) {
        const int rgi = tid >> 3;
        const int ii  = tid & 7;
        float d = 0.f, sx = 0.f, sr = 0.f;
#pragma unroll
        for (int h = 0; h < 2; h++) {
            const int ww2 = 2 * rgi + h;
#pragma unroll
            for (int l = 0; l < 8; l++) {
                d  += sRL[ww2][0][ii][l];
                sx += sRL[ww2][1][ii][l];
                sr += sRL[ww2][2][ii][l];
            }
        }
        const float denom = fmaxf(sqrtf(sx), EPSN) * fmaxf(sqrtf(sr), EPSN);
        float c = d / denom;
        c = warp_sum(c);
        if (tid == 0) g_rowPart[bid] = c;
    }

    // combine the 4 row groups per column, coalesced store to scratch
    for (int t = tid; t < 3 * WW; t += 256) {
        const int s    = t >> 9;        // stat
        const int col  = t & (WW - 1);
        const int cw2  = col >> 8;      // which column half
        const int cidx = col & 255;
        const int p    = cidx >> 2;
        const int j    = cidx & 3;
        float v = sColP[0 + cw2][s][p][j]
                + sColP[2 + cw2][s][p][j]
                + sColP[4 + cw2][s][p][j]
                + sColP[6 + cw2][s][p][j];
        g_colPart[img][chunk][s][col] = v;
    }
}

// ---------------------------------------------------------------------------
// Kernel 2: finish columns (one CTA per image), last CTA writes final scalar.
// ---------------------------------------------------------------------------
__global__ __launch_bounds__(512) void spl_pass2(float* __restrict__ out)
{
    const int img  = blockIdx.x;
    const int wcol = threadIdx.x;

    float d = 0.f, sx = 0.f, sr = 0.f;
#pragma unroll
    for (int ch = 0; ch < NCHUNK; ch++) {
        d  += g_colPart[img][ch][0][wcol];
        sx += g_colPart[img][ch][1][wcol];
        sr += g_colPart[img][ch][2][wcol];
    }
    const float denom = fmaxf(sqrtf(sx), EPSN) * fmaxf(sqrtf(sr), EPSN);
    double c = (double)(d / denom);

    __shared__ double sred[16];
    const int lane = wcol & 31, wp = wcol >> 5;
#pragma unroll
    for (int o = 16; o > 0; o >>= 1)
        c += __shfl_xor_sync(0xFFFFFFFFu, c, o);
    if (lane == 0) sred[wp] = c;
    __syncthreads();
    if (wcol < 32) {
        double v = (wcol < 16) ? sred[wcol] : 0.0;
#pragma unroll
        for (int o = 8; o > 0; o >>= 1)
            v += __shfl_xor_sync(0xFFFFFFFFu, v, o);
        if (wcol == 0) g_imgColSum[img] = v;
    }

    // last-block final reduction
    __shared__ bool sLast;
    __threadfence();
    __syncthreads();
    if (threadIdx.x == 0) {
        unsigned int prev = atomicAdd(&g_cnt, 1u);
        sLast = (prev == NIMG - 1);
    }
    __syncthreads();
    if (!sLast) return;

    double s = 0.0;
    for (int i = threadIdx.x; i < NCTA1; i += 512) s += (double)g_rowPart[i];
    if (threadIdx.x < NIMG) s += g_imgColSum[threadIdx.x];

#pragma unroll
    for (int o = 16; o > 0; o >>= 1)
        s += __shfl_xor_sync(0xFFFFFFFFu, s, o);
    if (lane == 0) sred[wp] = s;
    __syncthreads();
    if (threadIdx.x < 32) {
        double v = (threadIdx.x < 16) ? sred[threadIdx.x] : 0.0;
#pragma unroll
        for (int o = 8; o > 0; o >>= 1)
            v += __shfl_xor_sync(0xFFFFFFFFu, v, o);
        if (threadIdx.x == 0) out[0] = (float)(-v / 8192.0);
    }
}

extern "C" void kernel_launch(void* const* d_in, const int* in_sizes, int n_in,
                              void* d_out, int out_size)
{
    const float* x   = (const float*)d_in[0];
    const float* ref = (const float*)d_in[1];
    float* out = (float*)d_out;

    spl_pass1<<<NCTA1, 256>>>(x, ref);
    spl_pass2<<<NIMG, 512>>>(out);
}